// round 1
// baseline (speedup 1.0000x reference)
#include <cuda_runtime.h>
#include <math.h>
#include <float.h>

#define BB 4
#define NP0 4096
#define NEWP 1152
#define MAXN (NP0 + 10*NEWP)     // 15616
#define GD 256
#define HD 128
#define KSEL 64
#define NSTEPS 10
#define REFO (NEWP*3)            // 3456

// ---------------- device scratch (static: no allocation) ----------------
__device__ float    g_canvas[BB][MAXN][3];
__device__ float    g_F2T[128][BB*MAXN];      // encoder layer-2 activations, transposed (32MB)
__device__ unsigned g_gfenc[BB][GD];
__device__ float    g_gfeat[BB][GD];
__device__ float    g_h[BB][HD];
__device__ float    g_c[BB][HD];
__device__ float    g_attbias[BB][128];
__device__ float    g_scores[BB][MAXN];
__device__ float    g_center[BB][3];
__device__ float    g_patch[BB][3];
__device__ float    g_dist[BB][MAXN];
__device__ float    g_gates[BB][4*HD];
__device__ float    g_hid[BB][HD];
__device__ double   g_acc[4];

// monotone float<->uint encoding (for atomicMax over signed floats)
__device__ __forceinline__ unsigned fenc(float f){
    unsigned u = __float_as_uint(f);
    return (u & 0x80000000u) ? ~u : (u | 0x80000000u);
}
__device__ __forceinline__ float fdec(unsigned e){
    unsigned u = (e & 0x80000000u) ? (e & 0x7fffffffu) : ~e;
    return __uint_as_float(u);
}

// ---------------- init ----------------
__global__ void k_init(const float* __restrict__ points){
    int i = blockIdx.x*blockDim.x + threadIdx.x;
    if(i < BB*NP0*3){
        int b = i/(NP0*3); int r = i - b*(NP0*3);
        g_canvas[b][r/3][r%3] = points[i];
    }
    if(i < BB*HD){ g_h[i/HD][i%HD] = 0.f; g_c[i/HD][i%HD] = 0.f; }
    if(i < 4) g_acc[i] = 0.0;
}

__global__ void k_gfinit(){
    int i = blockIdx.x*blockDim.x + threadIdx.x;
    if(i < BB*GD) ((unsigned*)g_gfenc)[i] = fenc(-FLT_MAX);
}

// ---------------- encoder layers 1-2 (per point) ----------------
__global__ void k_enc12(const float* __restrict__ w1, const float* __restrict__ b1,
                        const float* __restrict__ w2, const float* __restrict__ b2, int N){
    __shared__ float s_w1[192];
    __shared__ float s_b1[64];
    __shared__ float s_w2[64*128];
    __shared__ float s_b2[128];
    int tid = threadIdx.x;
    for(int i=tid;i<192;i+=256) s_w1[i]=w1[i];
    if(tid<64)  s_b1[tid]=b1[tid];
    if(tid<128) s_b2[tid]=b2[tid];
    for(int i=tid;i<8192;i+=256) s_w2[i]=w2[i];
    __syncthreads();

    int p = blockIdx.x*256 + tid;
    if(p >= BB*N) return;
    int b = p / N, n = p - b*N;
    float x = g_canvas[b][n][0], y = g_canvas[b][n][1], z = g_canvas[b][n][2];

    float f1[64];
    #pragma unroll
    for(int o=0;o<64;o++)
        f1[o] = fmaxf(0.f, s_b1[o] + x*s_w1[o] + y*s_w1[64+o] + z*s_w1[128+o]);

    size_t col = (size_t)b*MAXN + n;
    for(int j=0;j<128;j+=4){
        float a0=s_b2[j], a1=s_b2[j+1], a2=s_b2[j+2], a3=s_b2[j+3];
        #pragma unroll
        for(int k=0;k<64;k++){
            float4 w = *(const float4*)&s_w2[k*128 + j];
            float f = f1[k];
            a0 += f*w.x; a1 += f*w.y; a2 += f*w.z; a3 += f*w.w;
        }
        g_F2T[j  ][col] = fmaxf(a0,0.f);
        g_F2T[j+1][col] = fmaxf(a1,0.f);
        g_F2T[j+2][col] = fmaxf(a2,0.f);
        g_F2T[j+3][col] = fmaxf(a3,0.f);
    }
}

// ---------------- encoder layer 3 GEMM + channel max (gfeat) ----------------
// grid (BB, N/64), block 256.  Tile: 64 points x 256 channels, K=128.
__global__ void k_enc3(const float* __restrict__ w3, const float* __restrict__ b3){
    __shared__ float sF[128*64];   // [k][p]
    int b = blockIdx.x;
    int pbase = blockIdx.y*64;
    int tid = threadIdx.x;
    size_t base = (size_t)b*MAXN + pbase;
    for(int i=tid;i<128*64;i+=256){
        int k = i>>6, p = i&63;
        sF[i] = g_F2T[k][base + p];
    }
    __syncthreads();

    int chb = (tid & 31) * 8;   // 8 consecutive channels
    int pg  = tid >> 5;         // point group 0..7 (8 points each)
    float acc[8][8];
    #pragma unroll
    for(int i=0;i<8;i++)
        #pragma unroll
        for(int j=0;j<8;j++) acc[i][j]=0.f;

    const float* w3p = w3 + chb;
    for(int k=0;k<128;k++){
        float4 wa = *(const float4*)(w3p + k*256);
        float4 wb = *(const float4*)(w3p + k*256 + 4);
        const float* fp = &sF[k*64 + pg*8];
        #pragma unroll
        for(int i=0;i<8;i++){
            float f = fp[i];
            acc[i][0]+=f*wa.x; acc[i][1]+=f*wa.y; acc[i][2]+=f*wa.z; acc[i][3]+=f*wa.w;
            acc[i][4]+=f*wb.x; acc[i][5]+=f*wb.y; acc[i][6]+=f*wb.z; acc[i][7]+=f*wb.w;
        }
    }
    float m[8];
    #pragma unroll
    for(int j=0;j<8;j++){
        float mm = acc[0][j];
        #pragma unroll
        for(int i=1;i<8;i++) mm = fmaxf(mm, acc[i][j]);
        m[j] = mm + b3[chb+j];    // max(a_i)+b == max(a_i+b)
    }
    __syncthreads();
    #pragma unroll
    for(int j=0;j<8;j++) sF[pg*256 + chb + j] = m[j];
    __syncthreads();
    {
        int ch = tid;   // 256 channels
        float mm = sF[ch];
        #pragma unroll
        for(int g=1;g<8;g++) mm = fmaxf(mm, sF[g*256 + ch]);
        atomicMax(&g_gfenc[b][ch], fenc(mm));
    }
}

// ---------------- attention per-batch precompute (decode gfeat + constant part of layer1) --
__global__ void k_attpre(const float* __restrict__ att_w1, const float* __restrict__ att_b1){
    int tid = threadIdx.x;
    for(int i=tid;i<BB*GD;i+=512)
        g_gfeat[i>>8][i&255] = fdec(g_gfenc[i>>8][i&255]);
    __syncthreads();
    int b = tid>>7, j = tid&127;
    float a = att_b1[j];
    for(int k=0;k<GD;k++) a += g_gfeat[b][k] * att_w1[(3+k)*128 + j];
    for(int k=0;k<HD;k++) a += g_h[b][k]     * att_w1[(259+k)*128 + j];
    g_attbias[b][j] = a;
}

// ---------------- attention score per point ----------------
__global__ void k_attscore(const float* __restrict__ att_w1, const float* __restrict__ att_w2,
                           const float* __restrict__ att_b2, int N){
    __shared__ float4 s_pk[128];       // {w1x,w1y,w1z,w2} per hidden unit
    __shared__ float  s_ab[BB][128];
    int tid = threadIdx.x;
    if(tid < 128)
        s_pk[tid] = make_float4(att_w1[tid], att_w1[128+tid], att_w1[256+tid], att_w2[tid]);
    for(int i=tid;i<BB*128;i+=256) s_ab[i>>7][i&127] = g_attbias[i>>7][i&127];
    __syncthreads();

    int p = blockIdx.x*256 + tid;
    if(p >= BB*N) return;
    int b = p/N, n = p - b*N;
    float x = g_canvas[b][n][0], y = g_canvas[b][n][1], z = g_canvas[b][n][2];
    float s = att_b2[0];
    #pragma unroll 4
    for(int j=0;j<128;j++){
        float4 w = s_pk[j];
        float hv = s_ab[b][j] + x*w.x + y*w.y + z*w.z;
        s += fmaxf(hv, 0.f) * w.w;
    }
    g_scores[b][n] = s;
}

// ---------------- softmax + center + dist (one block per batch) ----------------
__global__ void k_softcenter(int N){
    int b = blockIdx.x, tid = threadIdx.x;
    __shared__ float red[256];
    __shared__ float s_max, s_cx, s_cy, s_cz;
    float m = -FLT_MAX;
    for(int n=tid;n<N;n+=256) m = fmaxf(m, g_scores[b][n]);
    red[tid]=m; __syncthreads();
    for(int s=128;s>0;s>>=1){ if(tid<s) red[tid]=fmaxf(red[tid],red[tid+s]); __syncthreads(); }
    if(tid==0) s_max = red[0];
    __syncthreads();
    float mx = s_max;
    float se=0,sx=0,sy=0,sz=0;
    for(int n=tid;n<N;n+=256){
        float e = expf(g_scores[b][n]-mx);
        se += e;
        sx += e*g_canvas[b][n][0];
        sy += e*g_canvas[b][n][1];
        sz += e*g_canvas[b][n][2];
    }
    red[tid]=se; __syncthreads();
    for(int s=128;s>0;s>>=1){ if(tid<s) red[tid]+=red[tid+s]; __syncthreads(); }
    float se_t = red[0]; __syncthreads();
    red[tid]=sx; __syncthreads();
    for(int s=128;s>0;s>>=1){ if(tid<s) red[tid]+=red[tid+s]; __syncthreads(); }
    if(tid==0) s_cx = red[0]/se_t;
    __syncthreads();
    red[tid]=sy; __syncthreads();
    for(int s=128;s>0;s>>=1){ if(tid<s) red[tid]+=red[tid+s]; __syncthreads(); }
    if(tid==0) s_cy = red[0]/se_t;
    __syncthreads();
    red[tid]=sz; __syncthreads();
    for(int s=128;s>0;s>>=1){ if(tid<s) red[tid]+=red[tid+s]; __syncthreads(); }
    if(tid==0){
        s_cz = red[0]/se_t;
        g_center[b][0]=s_cx; g_center[b][1]=s_cy; g_center[b][2]=s_cz;
    }
    __syncthreads();
    float cx=s_cx, cy=s_cy, cz=s_cz;
    for(int n=tid;n<N;n+=256){
        float dx=g_canvas[b][n][0]-cx, dy=g_canvas[b][n][1]-cy, dz=g_canvas[b][n][2]-cz;
        g_dist[b][n] = sqrtf(dx*dx+dy*dy+dz*dz);
    }
}

// ---------------- exact top-K (K smallest dist) via uint binary search ----------------
__global__ void k_select(int N){
    int b = blockIdx.x, tid = threadIdx.x;
    __shared__ float red[256];
    __shared__ int   ired[256];
    __shared__ unsigned s_eqn;
    __shared__ int   s_eqi[256];
    __shared__ int   s_c1;
    __shared__ float s_sx, s_sy, s_sz;

    unsigned lo=0u, hi=0xFFFFFFFFu;
    while(lo < hi){
        unsigned mid = lo + ((hi-lo)>>1);
        int c=0;
        for(int n=tid;n<N;n+=256) if(__float_as_uint(g_dist[b][n]) <= mid) c++;
        ired[tid]=c; __syncthreads();
        for(int s=128;s>0;s>>=1){ if(tid<s) ired[tid]+=ired[tid+s]; __syncthreads(); }
        int tot = ired[0]; __syncthreads();
        if(tot >= KSEL) hi = mid; else lo = mid+1;
    }
    unsigned u = lo;   // bits of K-th smallest dist

    float sx=0,sy=0,sz=0; int c=0;
    for(int n=tid;n<N;n+=256){
        if(__float_as_uint(g_dist[b][n]) < u){
            c++; sx+=g_canvas[b][n][0]; sy+=g_canvas[b][n][1]; sz+=g_canvas[b][n][2];
        }
    }
    ired[tid]=c; red[tid]=sx; __syncthreads();
    for(int s=128;s>0;s>>=1){ if(tid<s){ired[tid]+=ired[tid+s]; red[tid]+=red[tid+s];} __syncthreads(); }
    if(tid==0){ s_c1=ired[0]; s_sx=red[0]; }
    __syncthreads();
    red[tid]=sy; __syncthreads();
    for(int s=128;s>0;s>>=1){ if(tid<s) red[tid]+=red[tid+s]; __syncthreads(); }
    if(tid==0) s_sy=red[0];
    __syncthreads();
    red[tid]=sz; __syncthreads();
    for(int s=128;s>0;s>>=1){ if(tid<s) red[tid]+=red[tid+s]; __syncthreads(); }
    if(tid==0){ s_sz=red[0]; s_eqn=0; }
    __syncthreads();
    for(int n=tid;n<N;n+=256){
        if(__float_as_uint(g_dist[b][n]) == u){
            unsigned p = atomicAdd(&s_eqn, 1u);
            if(p < 256) s_eqi[p] = n;
        }
    }
    __syncthreads();
    if(tid==0){
        int r = KSEL - s_c1;                 // boundary elems needed (index order, matches top_k ties)
        int m = min((int)s_eqn, 256);
        float ax=s_sx, ay=s_sy, az=s_sz;
        for(int it=0; it<r; it++){
            int best=-1, bi=0x7fffffff;
            for(int q=0;q<m;q++){ int v=s_eqi[q]; if(v>=0 && v<bi){bi=v;best=q;} }
            if(best<0) break;
            s_eqi[best] = -1;
            ax += g_canvas[b][bi][0]; ay += g_canvas[b][bi][1]; az += g_canvas[b][bi][2];
        }
        float inv = 1.f/KSEL;
        g_patch[b][0] = ax*inv - g_center[b][0];
        g_patch[b][1] = ay*inv - g_center[b][1];
        g_patch[b][2] = az*inv - g_center[b][2];
    }
}

// ---------------- LSTM gates (grid 4 x 128 threads) ----------------
__global__ void k_gates(const float* __restrict__ wih, const float* __restrict__ whh,
                        const float* __restrict__ bih, const float* __restrict__ bhh){
    __shared__ float s_in[BB][262];
    __shared__ float s_h[BB][HD];
    int tid = threadIdx.x;
    for(int i=tid;i<BB*262;i+=128){
        int b=i/262, k=i-b*262;
        float v;
        if(k < GD)        v = g_gfeat[b][k];
        else if(k < GD+3) v = g_center[b][k-GD];
        else              v = g_patch[b][k-GD-3];
        s_in[b][k]=v;
    }
    for(int i=tid;i<BB*HD;i+=128) s_h[i>>7][i&127]=g_h[i>>7][i&127];
    __syncthreads();
    int j = blockIdx.x*128 + tid;
    float base = bih[j] + bhh[j];
    float a0=base,a1=base,a2=base,a3=base;
    for(int k=0;k<262;k++){
        float w = wih[k*512 + j];
        a0 += s_in[0][k]*w; a1 += s_in[1][k]*w; a2 += s_in[2][k]*w; a3 += s_in[3][k]*w;
    }
    for(int k=0;k<HD;k++){
        float w = whh[k*512 + j];
        a0 += s_h[0][k]*w; a1 += s_h[1][k]*w; a2 += s_h[2][k]*w; a3 += s_h[3][k]*w;
    }
    g_gates[0][j]=a0; g_gates[1][j]=a1; g_gates[2][j]=a2; g_gates[3][j]=a3;
}

__global__ void k_lstm(){
    int tid = threadIdx.x;
    int b = tid>>7, j = tid&127;
    float gi=g_gates[b][j], gf=g_gates[b][HD+j], gg=g_gates[b][2*HD+j], go=g_gates[b][3*HD+j];
    float sgi=1.f/(1.f+expf(-gi)), sgf=1.f/(1.f+expf(-gf)), sgo=1.f/(1.f+expf(-go));
    float c = sgf*g_c[b][j] + sgi*tanhf(gg);
    g_c[b][j] = c;
    g_h[b][j] = sgo*tanhf(c);
}

// ---------------- refine decoder ----------------
__global__ void k_ref1(const float* __restrict__ ref_w1, const float* __restrict__ ref_b1){
    int tid = threadIdx.x;
    int b = tid>>7, j = tid&127;
    float a = ref_b1[j];
    for(int k=0;k<HD;k++) a += g_h[b][k]*ref_w1[k*128+j];
    g_hid[b][j] = fmaxf(a, 0.f);
}

__global__ void k_ref2(const float* __restrict__ ref_w2, const float* __restrict__ ref_b2, int N){
    int o = blockIdx.x*256 + threadIdx.x;
    if(o >= BB*REFO) return;
    int b = o/REFO, q = o - b*REFO;
    float a = ref_b2[q];
    const float* h = g_hid[b];
    for(int k=0;k<HD;k++) a += h[k]*ref_w2[k*REFO + q];
    int pt = q/3, d = q - 3*pt;
    g_canvas[b][N+pt][d] = a*0.02f + g_center[b][d];
}

// ---------------- chamfer: one direction per launch ----------------
// sel: 0 = canvas, 1 = gt
__global__ void k_cham(const float* __restrict__ gt, int xsel, int xoff, int Nx,
                       int ysel, int yoff, int Ny, int ai){
    __shared__ float sy3[3*1024];
    __shared__ float red[256];
    int b = blockIdx.y, tid = threadIdx.x;
    int n = blockIdx.x*256 + tid;
    float x0=0,x1=0,x2=0;
    bool act = n < Nx;
    if(act){
        const float* p = (xsel==0) ? &g_canvas[b][xoff+n][0]
                                   : gt + ((size_t)b*NP0 + xoff + n)*3;
        x0=p[0]; x1=p[1]; x2=p[2];
    }
    float mn = FLT_MAX;
    for(int t=0;t<Ny;t+=1024){
        int cnt = min(1024, Ny-t);
        __syncthreads();
        const float* ys = (ysel==0) ? &g_canvas[b][yoff+t][0]
                                    : gt + ((size_t)b*NP0 + yoff + t)*3;
        for(int i=tid;i<cnt*3;i+=256) sy3[i]=ys[i];
        __syncthreads();
        if(act){
            #pragma unroll 4
            for(int j=0;j<cnt;j++){
                float d0=x0-sy3[3*j], d1=x1-sy3[3*j+1], d2=x2-sy3[3*j+2];
                mn = fminf(mn, d0*d0 + d1*d1 + d2*d2);
            }
        }
    }
    red[tid] = act ? mn : 0.f;
    __syncthreads();
    for(int s=128;s>0;s>>=1){ if(tid<s) red[tid]+=red[tid+s]; __syncthreads(); }
    if(tid==0) atomicAdd(&g_acc[ai], (double)red[0]);
}

__global__ void k_final(float* __restrict__ out){
    double cd_in  = g_acc[0]/(4.0*NP0)          + g_acc[1]/(4.0*NP0);
    double cd_new = g_acc[2]/(4.0*(10.0*NEWP))  + g_acc[3]/(4.0*NP0);
    out[0] = (float)(0.1*cd_in + 1.0*cd_new);
}

// ---------------- host launch ----------------
extern "C" void kernel_launch(void* const* d_in, const int* in_sizes, int n_in,
                              void* d_out, int out_size){
    const float* points   = (const float*)d_in[0];
    const float* gt       = (const float*)d_in[1];
    const float* enc_w1   = (const float*)d_in[2];
    const float* enc_b1   = (const float*)d_in[3];
    const float* enc_w2   = (const float*)d_in[4];
    const float* enc_b2   = (const float*)d_in[5];
    const float* enc_w3   = (const float*)d_in[6];
    const float* enc_b3   = (const float*)d_in[7];
    const float* att_w1   = (const float*)d_in[8];
    const float* att_b1   = (const float*)d_in[9];
    const float* att_w2   = (const float*)d_in[10];
    const float* att_b2   = (const float*)d_in[11];
    const float* lstm_wih = (const float*)d_in[12];
    const float* lstm_whh = (const float*)d_in[13];
    const float* lstm_bih = (const float*)d_in[14];
    const float* lstm_bhh = (const float*)d_in[15];
    const float* ref_w1   = (const float*)d_in[16];
    const float* ref_b1   = (const float*)d_in[17];
    const float* ref_w2   = (const float*)d_in[18];
    const float* ref_b2   = (const float*)d_in[19];

    k_init<<<(BB*NP0*3 + 255)/256, 256>>>(points);

    int N = NP0;
    for(int s=0;s<NSTEPS;s++){
        int P = BB*N;
        k_gfinit<<<4,256>>>();
        k_enc12<<<(P+255)/256, 256>>>(enc_w1, enc_b1, enc_w2, enc_b2, N);
        dim3 g3(BB, N/64);
        k_enc3<<<g3, 256>>>(enc_w3, enc_b3);
        k_attpre<<<1,512>>>(att_w1, att_b1);
        k_attscore<<<(P+255)/256, 256>>>(att_w1, att_w2, att_b2, N);
        k_softcenter<<<BB,256>>>(N);
        k_select<<<BB,256>>>(N);
        k_gates<<<4,128>>>(lstm_wih, lstm_whh, lstm_bih, lstm_bhh);
        k_lstm<<<1,512>>>();
        k_ref1<<<1,512>>>(ref_w1, ref_b1);
        k_ref2<<<(BB*REFO+255)/256, 256>>>(ref_w2, ref_b2, N);
        N += NEWP;
    }

    int NN = N - NP0;  // 11520 new points
    // chamfer(p_input, gt): both directions
    k_cham<<<dim3((NP0+255)/256, BB), 256>>>(gt, 0, 0,   NP0, 1, 0,   NP0, 0);
    k_cham<<<dim3((NP0+255)/256, BB), 256>>>(gt, 1, 0,   NP0, 0, 0,   NP0, 1);
    // chamfer(p_new, gt): both directions
    k_cham<<<dim3((NN +255)/256, BB), 256>>>(gt, 0, NP0, NN,  1, 0,   NP0, 2);
    k_cham<<<dim3((NP0+255)/256, BB), 256>>>(gt, 1, 0,   NP0, 0, NP0, NN,  3);

    k_final<<<1,1>>>((float*)d_out);
}